// round 15
// baseline (speedup 1.0000x reference)
#include <cuda_runtime.h>
#include <cuda_bf16.h>
#include <math.h>
#include <stdint.h>

namespace {
constexpr int N      = 256;
constexpr int NSTEPS = 32;
constexpr int NIMG   = 384;                  // 128 batch * 3 channels

// ---- k_mm smem maps (bytes) — R12 champion ----
constexpr int M1_AH   = 0;
constexpr int M1_AL   = 10240;
constexpr int M1_BS   = 20480;
constexpr int M1_BUF  = 37376;
constexpr int M1_CBH  = 2 * M1_BUF;          // 74752
constexpr int M1_CBL  = M1_CBH + 8704;
constexpr int M1_SMEM = M1_CBL + 8704;       // 92160
constexpr int M2_AS   = 0;
constexpr int M2_BH   = 18432;
constexpr int M2_BL   = 28672;
constexpr int M2_BUF  = 38912;
constexpr int M2_CAH  = 2 * M2_BUF;          // 77824
constexpr int M2_CAL  = M2_CAH + 10240;
constexpr int M2_SMEM = M2_CAL + 10240;      // 98304
}

// ---------------- device globals ----------------
__device__ float g_E[NSTEPS * N];            // per-step decay e_k
__device__ float g_CS[1024];                 // cos(pi*p/512)
__device__ float g_SN[1024];                 // sin(pi*p/512)
__device__ float g_F[NSTEPS * 1024];         // per step: Co[512] | So[512] (odd-m series)
__device__ __align__(16) __nv_bfloat16 g_Mh[NSTEPS * N * N];
__device__ __align__(16) __nv_bfloat16 g_Ml[NSTEPS * N * N];
__device__ __align__(16) float g_T[NIMG * N * N];     // fp32 intermediate

// ---------------- helpers ----------------
__device__ __forceinline__ uint32_t smem_u32(const void* p) {
    uint32_t a;
    asm("{ .reg .u64 t; cvta.to.shared.u64 t, %1; cvt.u32.u64 %0, t; }" : "=r"(a) : "l"(p));
    return a;
}
__device__ __forceinline__ void cp16(uint32_t s, const void* g) {
    asm volatile("cp.async.cg.shared.global [%0], [%1], 16;" :: "r"(s), "l"(g) : "memory");
}
__device__ __forceinline__ void cp_commit() {
    asm volatile("cp.async.commit_group;" ::: "memory");
}
__device__ __forceinline__ void cp_wait0() {
    asm volatile("cp.async.wait_group 0;" ::: "memory");
}
__device__ __forceinline__ void ldsm4(uint32_t* r, uint32_t a) {
    asm volatile("ldmatrix.sync.aligned.m8n8.x4.shared.b16 {%0,%1,%2,%3}, [%4];"
                 : "=r"(r[0]), "=r"(r[1]), "=r"(r[2]), "=r"(r[3]) : "r"(a));
}
__device__ __forceinline__ void ldsm4t(uint32_t* r, uint32_t a) {
    asm volatile("ldmatrix.sync.aligned.m8n8.x4.trans.shared.b16 {%0,%1,%2,%3}, [%4];"
                 : "=r"(r[0]), "=r"(r[1]), "=r"(r[2]), "=r"(r[3]) : "r"(a));
}
__device__ __forceinline__ void mma_bf16(float* d, const uint32_t* a, uint32_t b0, uint32_t b1) {
    asm volatile(
        "mma.sync.aligned.m16n8k16.row.col.f32.bf16.bf16.f32 "
        "{%0,%1,%2,%3}, {%4,%5,%6,%7}, {%8,%9}, {%0,%1,%2,%3};"
        : "+f"(d[0]), "+f"(d[1]), "+f"(d[2]), "+f"(d[3])
        : "r"(a[0]), "r"(a[1]), "r"(a[2]), "r"(a[3]), "r"(b0), "r"(b1));
}
__device__ __forceinline__ uint32_t pkbf2(float a, float b) {
    __nv_bfloat162 t = __floats2bfloat162_rn(a, b);
    return reinterpret_cast<uint32_t&>(t);
}
__device__ __forceinline__ void split8(const float* v, uint4& H, uint4& L) {
    float h[8], l[8];
#pragma unroll
    for (int i = 0; i < 8; i++) {
        __nv_bfloat16 b = __float2bfloat16_rn(v[i]);
        h[i] = __bfloat162float(b);
        l[i] = v[i] - h[i];
    }
    H = make_uint4(pkbf2(h[0], h[1]), pkbf2(h[2], h[3]), pkbf2(h[4], h[5]), pkbf2(h[6], h[7]));
    L = make_uint4(pkbf2(l[0], l[1]), pkbf2(l[2], l[3]), pkbf2(l[4], l[5]), pkbf2(l[6], l[7]));
}
__device__ __forceinline__ void split4(float4 v, uint2& H, uint2& L) {
    float vv[4] = {v.x, v.y, v.z, v.w};
    float h[4], l[4];
#pragma unroll
    for (int i = 0; i < 4; i++) {
        __nv_bfloat16 b = __float2bfloat16_rn(vv[i]);
        h[i] = __bfloat162float(b);
        l[i] = vv[i] - h[i];
    }
    H = make_uint2(pkbf2(h[0], h[1]), pkbf2(h[2], h[3]));
    L = make_uint2(pkbf2(l[0], l[1]), pkbf2(l[2], l[3]));
}

// ---------------- init: e table + trig tables ----------------
__global__ void k_init(const float* __restrict__ sigmas) {
    const int s = blockIdx.x, k = threadIdx.x;
    float sig = sigmas[s];
    float t = 0.5f * sig * sig;
    float f = (float)M_PI * (float)k / (float)N;
    g_E[s * N + k] = expf(-f * f * t);
    if (s == 0) {
#pragma unroll
        for (int i = 0; i < 4; i++) {
            int p = k + i * 256;
            double a = M_PI * (double)p / 512.0;
            g_CS[p] = (float)cos(a);
            g_SN[p] = (float)sin(a);
        }
    }
}

// ---------------- series: Co/So per step (odd m = 2q+1) ----------------
// C(m) = sum_k w_k cos(pi*k*m/512), S(m) = sum_k w_k sin(pi*k*m/512),
// w_k = alpha_k * e_k / N  (alpha_0 = 1/sqrt(2)).
__global__ void k_F(void) {
    __shared__ float cs[1024], sn[1024], w[256];
    const int s = blockIdx.x, t = threadIdx.x;
#pragma unroll
    for (int i = 0; i < 4; i++) {
        cs[t + i * 256] = g_CS[t + i * 256];
        sn[t + i * 256] = g_SN[t + i * 256];
    }
    float e = g_E[s * N + t];
    w[t] = e * ((t == 0) ? 0.70710678118654752f : 1.0f) / (float)N;
    __syncthreads();
#pragma unroll 1
    for (int half = 0; half < 2; half++) {
        int q = t + half * 256;
        int m = 2 * q + 1;
        float ac = 0.0f, as = 0.0f;
        int idx = 0;
#pragma unroll 4
        for (int k = 0; k < 256; k++) {
            float wk = w[k];
            ac = fmaf(wk, cs[idx], ac);
            as = fmaf(wk, sn[idx], as);
            idx = (idx + m) & 1023;
        }
        g_F[s * 1024 + q]       = ac;
        g_F[s * 1024 + 512 + q] = as;
    }
}

// ---------------- fill: M_ij = alpha_i*(cs[i]*(Co[qu]+Co[qv]) - sn[i]*(So[qu]+So[qv]))
// u = (2(i-j)-1) mod 1024, v = (2(i+j)+1) mod 1024 (both odd); q = m>>1.
// grid (8, NSTEPS): 32 rows per CTA. Epilogue splits to bf16 hi/lo.
__global__ void k_fill(void) {
    __shared__ float Co[512], So[512];
    const int s = blockIdx.y, rb = blockIdx.x, t = threadIdx.x;
#pragma unroll
    for (int i = 0; i < 2; i++) {
        Co[t + i * 256] = g_F[s * 1024 + t + i * 256];
        So[t + i * 256] = g_F[s * 1024 + 512 + t + i * 256];
    }
    __syncthreads();

    const int r  = rb * 32 + (t >> 3);
    const int j0 = (t & 7) * 32;
    const float ar  = (r == 0) ? 0.70710678118654752f : 1.0f;
    const float cr  = ar * g_CS[r];
    const float sr  = ar * g_SN[r];

    __nv_bfloat16* mh = g_Mh + ((size_t)s * N + r) * N;
    __nv_bfloat16* ml = g_Ml + ((size_t)s * N + r) * N;

#pragma unroll
    for (int g = 0; g < 8; g++) {
        float vals[4];
#pragma unroll
        for (int jj = 0; jj < 4; jj++) {
            int j = j0 + g * 4 + jj;
            int qu = ((2 * (r - j) - 1) & 1023) >> 1;
            int qv = ((2 * (r + j) + 1) & 1023) >> 1;
            vals[jj] = cr * (Co[qu] + Co[qv]) - sr * (So[qu] + So[qv]);
        }
        float4 v4 = make_float4(vals[0], vals[1], vals[2], vals[3]);
        uint2 H, L;
        split4(v4, H, L);
        *(uint2*)&mh[j0 + g * 4] = H;
        *(uint2*)&ml[j0 + g * 4] = L;
    }
}

// ---------------- MMA kernel (R12 champion, verbatim) ----------------
// grid (NIMG, 2, 2) = (z, h, nh); 256 threads; warp grid 4m x 2n; warp tile 32x64.
// MODE 1: T[z](h,nh) = M[s](h rows) * X[z]        (B = fp32 X, split in-kernel)
// MODE 2: out[z](h,nh) = T[z](h rows) * M[s]^T    (A = fp32 T, split in-kernel)
template <int MODE>
__global__ __launch_bounds__(256, 2) void k_mm(const float* __restrict__ Xf,
                                               float* __restrict__ Out,
                                               const int* __restrict__ steps) {
    extern __shared__ char sm[];
    const int z = blockIdx.x, h = blockIdx.y, nh = blockIdx.z;
    const int s = steps[z / 3];
    const int t = threadIdx.x, lane = t & 31, wid = t >> 5;
    const int wm = wid >> 1, wn = wid & 1;
    const uint32_t sb = smem_u32(sm);
    const int lr = lane & 15, lc8 = (lane >> 4) * 8;

    constexpr int BUFSZ = (MODE == 1) ? M1_BUF : M2_BUF;

    const char* Mh_g = (const char*)(g_Mh + (size_t)s * N * N);
    const char* Ml_g = (const char*)(g_Ml + (size_t)s * N * N);
    const float* F_g = (MODE == 1) ? (Xf + (size_t)z * N * N)
                                   : (g_T + (size_t)z * N * N);

    auto stage = [&](int kc, int b) {
        const uint32_t bo = sb + b * BUFSZ;
        if (MODE == 1) {
#pragma unroll
            for (int i = 0; i < 2; i++) {
                int c = t + i * 256, r = c >> 2, q = c & 3;
                size_t go = (size_t)(h * 128 + r) * 512 + kc * 64 + q * 16;
                cp16(bo + M1_AH + r * 80 + q * 16, Mh_g + go);
                cp16(bo + M1_AL + r * 80 + q * 16, Ml_g + go);
            }
#pragma unroll
            for (int i = 0; i < 4; i++) {
                int c = t + i * 256, r = c >> 5, q = c & 31;
                size_t go = (size_t)(kc * 32 + r) * 1024 + nh * 512 + q * 16;
                cp16(bo + M1_BS + r * 528 + q * 16, (const char*)F_g + go);
            }
        } else {
#pragma unroll
            for (int i = 0; i < 4; i++) {
                int c = t + i * 256, r = c >> 3, q = c & 7;
                size_t go = (size_t)(h * 128 + r) * 1024 + kc * 128 + q * 16;
                cp16(bo + M2_AS + r * 144 + q * 16, (const char*)F_g + go);
            }
#pragma unroll
            for (int i = 0; i < 2; i++) {
                int c = t + i * 256, r = c >> 2, q = c & 3;
                size_t go = (size_t)(nh * 128 + r) * 512 + kc * 64 + q * 16;
                cp16(bo + M2_BH + r * 80 + q * 16, Mh_g + go);
                cp16(bo + M2_BL + r * 80 + q * 16, Ml_g + go);
            }
        }
        cp_commit();
    };

    float acc[2][8][4];
#pragma unroll
    for (int a = 0; a < 2; a++)
#pragma unroll
        for (int b = 0; b < 8; b++)
#pragma unroll
            for (int c = 0; c < 4; c++) acc[a][b][c] = 0.0f;

    stage(0, 0);

#pragma unroll 1
    for (int kc = 0; kc < 8; kc++) {
        cp_wait0();
        __syncthreads();
        if (kc < 7) stage(kc + 1, (kc + 1) & 1);
        const uint32_t bo = sb + (kc & 1) * BUFSZ;
        const char* bufc = sm + (kc & 1) * BUFSZ;

        if (MODE == 1) {
            int r = t >> 3, cs = (t & 7) * 16;
            const float* src = (const float*)(bufc + M1_BS) + r * 132 + cs;
            char* dh = sm + M1_CBH + (r * 136 + cs) * 2;
            char* dl = sm + M1_CBL + (r * 136 + cs) * 2;
#pragma unroll
            for (int g = 0; g < 2; g++) {
                float4 v0 = *(const float4*)&src[g * 8];
                float4 v1 = *(const float4*)&src[g * 8 + 4];
                float v[8] = {v0.x, v0.y, v0.z, v0.w, v1.x, v1.y, v1.z, v1.w};
                uint4 H, L; split8(v, H, L);
                *(uint4*)(dh + g * 16) = H;
                *(uint4*)(dl + g * 16) = L;
            }
        } else {
            int r = t >> 1, cs = (t & 1) * 16;
            const float* src = (const float*)(bufc + M2_AS) + r * 36 + cs;
            char* dh = sm + M2_CAH + (r * 40 + cs) * 2;
            char* dl = sm + M2_CAL + (r * 40 + cs) * 2;
#pragma unroll
            for (int g = 0; g < 2; g++) {
                float4 v0 = *(const float4*)&src[g * 8];
                float4 v1 = *(const float4*)&src[g * 8 + 4];
                float v[8] = {v0.x, v0.y, v0.z, v0.w, v1.x, v1.y, v1.z, v1.w};
                uint4 H, L; split8(v, H, L);
                *(uint4*)(dh + g * 16) = H;
                *(uint4*)(dl + g * 16) = L;
            }
        }
        __syncthreads();

#pragma unroll
        for (int ks = 0; ks < 2; ks++) {
            uint32_t Ah[2][4], Al2[2][4], Bf[4][4];
#pragma unroll
            for (int mi = 0; mi < 2; mi++) {
                uint32_t a;
                if (MODE == 1)
                    a = bo + M1_AH + ((wm * 32 + mi * 16 + lr) * 40 + ks * 16 + lc8) * 2;
                else
                    a = sb + M2_CAH + ((wm * 32 + mi * 16 + lr) * 40 + ks * 16 + lc8) * 2;
                ldsm4(Ah[mi], a);
                ldsm4(Al2[mi], a + ((MODE == 1) ? (M1_AL - M1_AH) : (M2_CAL - M2_CAH)));
            }
#pragma unroll
            for (int nj = 0; nj < 4; nj++) {
                if (MODE == 1) {
                    uint32_t a = sb + M1_CBH + ((ks * 16 + lr) * 136 + wn * 64 + nj * 16 + lc8) * 2;
                    ldsm4t(Bf[nj], a);
                } else {
                    uint32_t a = bo + M2_BH + ((wn * 64 + nj * 16 + lr) * 40 + ks * 16 + lc8) * 2;
                    ldsm4(Bf[nj], a);
                }
            }
            const int p0 = 0, p1 = (MODE == 1) ? 1 : 2;
            const int p2 = (MODE == 1) ? 2 : 1, p3 = 3;
#pragma unroll
            for (int mi = 0; mi < 2; mi++)
#pragma unroll
                for (int nj = 0; nj < 4; nj++) {
                    mma_bf16(acc[mi][nj * 2],     Ah[mi], Bf[nj][p0], Bf[nj][p1]);
                    mma_bf16(acc[mi][nj * 2 + 1], Ah[mi], Bf[nj][p2], Bf[nj][p3]);
                }
#pragma unroll
            for (int mi = 0; mi < 2; mi++)
#pragma unroll
                for (int nj = 0; nj < 4; nj++) {
                    mma_bf16(acc[mi][nj * 2],     Al2[mi], Bf[nj][p0], Bf[nj][p1]);
                    mma_bf16(acc[mi][nj * 2 + 1], Al2[mi], Bf[nj][p2], Bf[nj][p3]);
                }
#pragma unroll
            for (int nj = 0; nj < 4; nj++) {
                if (MODE == 1) {
                    uint32_t a = sb + M1_CBL + ((ks * 16 + lr) * 136 + wn * 64 + nj * 16 + lc8) * 2;
                    ldsm4t(Bf[nj], a);
                } else {
                    uint32_t a = bo + M2_BL + ((wn * 64 + nj * 16 + lr) * 40 + ks * 16 + lc8) * 2;
                    ldsm4(Bf[nj], a);
                }
            }
#pragma unroll
            for (int mi = 0; mi < 2; mi++)
#pragma unroll
                for (int nj = 0; nj < 4; nj++) {
                    mma_bf16(acc[mi][nj * 2],     Ah[mi], Bf[nj][p0], Bf[nj][p1]);
                    mma_bf16(acc[mi][nj * 2 + 1], Ah[mi], Bf[nj][p2], Bf[nj][p3]);
                }
        }
        __syncthreads();
    }

    float* dst = ((MODE == 1) ? g_T : Out) + (size_t)z * N * N;
#pragma unroll
    for (int mi = 0; mi < 2; mi++)
#pragma unroll
        for (int nf = 0; nf < 8; nf++) {
            int col = nh * 128 + wn * 64 + nf * 8 + (lane & 3) * 2;
#pragma unroll
            for (int rg = 0; rg < 2; rg++) {
                int row = h * 128 + wm * 32 + mi * 16 + rg * 8 + (lane >> 2);
                *(float2*)&dst[(size_t)row * N + col] =
                    make_float2(acc[mi][nf][rg * 2], acc[mi][nf][rg * 2 + 1]);
            }
        }
}

// ---------------- host ----------------
extern "C" void kernel_launch(void* const* d_in, const int* in_sizes, int n_in,
                              void* d_out, int out_size) {
    const float* x = nullptr;
    const float* sigmas = nullptr;
    const int* steps = nullptr;
    for (int i = 0; i < n_in; i++) {
        if (in_sizes[i] == NSTEPS)      sigmas = (const float*)d_in[i];
        else if (in_sizes[i] == 128)    steps  = (const int*)d_in[i];
        else                            x      = (const float*)d_in[i];
    }
    float* out = (float*)d_out;

    cudaFuncSetAttribute(k_mm<1>, cudaFuncAttributeMaxDynamicSharedMemorySize, M1_SMEM);
    cudaFuncSetAttribute(k_mm<2>, cudaFuncAttributeMaxDynamicSharedMemorySize, M2_SMEM);

    k_init<<<NSTEPS, 256>>>(sigmas);
    k_F<<<NSTEPS, 256>>>();
    k_fill<<<dim3(8, NSTEPS), 256>>>();
    k_mm<1><<<dim3(NIMG, 2, 2), 256, M1_SMEM>>>(x, nullptr, steps);
    k_mm<2><<<dim3(NIMG, 2, 2), 256, M2_SMEM>>>(nullptr, out, steps);
}

// round 16
// speedup vs baseline: 1.0328x; 1.0328x over previous
#include <cuda_runtime.h>
#include <cuda_bf16.h>
#include <math.h>
#include <stdint.h>

namespace {
constexpr int N      = 256;
constexpr int NSTEPS = 32;
constexpr int NIMG   = 384;                  // 128 batch * 3 channels

// ---- k_mm smem maps (bytes) — R12 champion ----
constexpr int M1_AH   = 0;
constexpr int M1_AL   = 10240;
constexpr int M1_BS   = 20480;
constexpr int M1_BUF  = 37376;
constexpr int M1_CBH  = 2 * M1_BUF;          // 74752
constexpr int M1_CBL  = M1_CBH + 8704;
constexpr int M1_SMEM = M1_CBL + 8704;       // 92160
constexpr int M2_AS   = 0;
constexpr int M2_BH   = 18432;
constexpr int M2_BL   = 28672;
constexpr int M2_BUF  = 38912;
constexpr int M2_CAH  = 2 * M2_BUF;          // 77824
constexpr int M2_CAL  = M2_CAH + 10240;
constexpr int M2_SMEM = M2_CAL + 10240;      // 98304
}

// ---------------- device globals ----------------
__device__ float g_E[NSTEPS * N];            // per-step decay e_k
__device__ float g_CS[1024];                 // cos(pi*p/512)
__device__ float g_SN[1024];                 // sin(pi*p/512)
__device__ float g_F[NSTEPS * 1024];         // per step: Co[512] | So[512] (odd-m series)
__device__ __align__(16) __nv_bfloat16 g_Mh[NSTEPS * N * N];
__device__ __align__(16) __nv_bfloat16 g_Ml[NSTEPS * N * N];
__device__ __align__(16) float g_T[NIMG * N * N];     // fp32 intermediate

// ---------------- helpers ----------------
__device__ __forceinline__ uint32_t smem_u32(const void* p) {
    uint32_t a;
    asm("{ .reg .u64 t; cvta.to.shared.u64 t, %1; cvt.u32.u64 %0, t; }" : "=r"(a) : "l"(p));
    return a;
}
__device__ __forceinline__ void cp16(uint32_t s, const void* g) {
    asm volatile("cp.async.cg.shared.global [%0], [%1], 16;" :: "r"(s), "l"(g) : "memory");
}
__device__ __forceinline__ void cp_commit() {
    asm volatile("cp.async.commit_group;" ::: "memory");
}
__device__ __forceinline__ void cp_wait0() {
    asm volatile("cp.async.wait_group 0;" ::: "memory");
}
__device__ __forceinline__ void ldsm4(uint32_t* r, uint32_t a) {
    asm volatile("ldmatrix.sync.aligned.m8n8.x4.shared.b16 {%0,%1,%2,%3}, [%4];"
                 : "=r"(r[0]), "=r"(r[1]), "=r"(r[2]), "=r"(r[3]) : "r"(a));
}
__device__ __forceinline__ void ldsm4t(uint32_t* r, uint32_t a) {
    asm volatile("ldmatrix.sync.aligned.m8n8.x4.trans.shared.b16 {%0,%1,%2,%3}, [%4];"
                 : "=r"(r[0]), "=r"(r[1]), "=r"(r[2]), "=r"(r[3]) : "r"(a));
}
__device__ __forceinline__ void mma_bf16(float* d, const uint32_t* a, uint32_t b0, uint32_t b1) {
    asm volatile(
        "mma.sync.aligned.m16n8k16.row.col.f32.bf16.bf16.f32 "
        "{%0,%1,%2,%3}, {%4,%5,%6,%7}, {%8,%9}, {%0,%1,%2,%3};"
        : "+f"(d[0]), "+f"(d[1]), "+f"(d[2]), "+f"(d[3])
        : "r"(a[0]), "r"(a[1]), "r"(a[2]), "r"(a[3]), "r"(b0), "r"(b1));
}
__device__ __forceinline__ uint32_t pkbf2(float a, float b) {
    __nv_bfloat162 t = __floats2bfloat162_rn(a, b);
    return reinterpret_cast<uint32_t&>(t);
}
__device__ __forceinline__ void split8(const float* v, uint4& H, uint4& L) {
    float h[8], l[8];
#pragma unroll
    for (int i = 0; i < 8; i++) {
        __nv_bfloat16 b = __float2bfloat16_rn(v[i]);
        h[i] = __bfloat162float(b);
        l[i] = v[i] - h[i];
    }
    H = make_uint4(pkbf2(h[0], h[1]), pkbf2(h[2], h[3]), pkbf2(h[4], h[5]), pkbf2(h[6], h[7]));
    L = make_uint4(pkbf2(l[0], l[1]), pkbf2(l[2], l[3]), pkbf2(l[4], l[5]), pkbf2(l[6], l[7]));
}
__device__ __forceinline__ void split4(float4 v, uint2& H, uint2& L) {
    float vv[4] = {v.x, v.y, v.z, v.w};
    float h[4], l[4];
#pragma unroll
    for (int i = 0; i < 4; i++) {
        __nv_bfloat16 b = __float2bfloat16_rn(vv[i]);
        h[i] = __bfloat162float(b);
        l[i] = vv[i] - h[i];
    }
    H = make_uint2(pkbf2(h[0], h[1]), pkbf2(h[2], h[3]));
    L = make_uint2(pkbf2(l[0], l[1]), pkbf2(l[2], l[3]));
}

// ---------------- init: e table + trig tables ----------------
__global__ void k_init(const float* __restrict__ sigmas) {
    const int s = blockIdx.x, k = threadIdx.x;
    float sig = sigmas[s];
    float t = 0.5f * sig * sig;
    float f = (float)M_PI * (float)k / (float)N;
    g_E[s * N + k] = expf(-f * f * t);
    if (s == 0) {
#pragma unroll
        for (int i = 0; i < 4; i++) {
            int p = k + i * 256;
            double a = M_PI * (double)p / 512.0;
            g_CS[p] = (float)cos(a);
            g_SN[p] = (float)sin(a);
        }
    }
}

// ---------------- series: Co/So per step (odd m = 2q+1) ----------------
// C(m) = sum_k w_k cos(pi*k*m/512), S(m) = sum_k w_k sin(pi*k*m/512),
// w_k = alpha_k * e_k / N  (alpha_0 = 1/sqrt(2)).
// grid (NSTEPS, 2); each thread computes one q. Multiplicative indexing:
// idx = (k*m)&1023 per-iteration (independent) -> loads fully pipelined.
__global__ void k_F(void) {
    __shared__ float cs[1024], sn[1024], w[256];
    const int s = blockIdx.x, half = blockIdx.y, t = threadIdx.x;
#pragma unroll
    for (int i = 0; i < 4; i++) {
        cs[t + i * 256] = g_CS[t + i * 256];
        sn[t + i * 256] = g_SN[t + i * 256];
    }
    float e = g_E[s * N + t];
    w[t] = e * ((t == 0) ? 0.70710678118654752f : 1.0f) / (float)N;
    __syncthreads();

    const int q = half * 256 + t;
    const int m = 2 * q + 1;
    float ac = 0.0f, as = 0.0f;
#pragma unroll
    for (int k = 0; k < 256; k++) {
        int idx = (k * m) & 1023;
        float wk = w[k];
        ac = fmaf(wk, cs[idx], ac);
        as = fmaf(wk, sn[idx], as);
    }
    g_F[s * 1024 + q]       = ac;
    g_F[s * 1024 + 512 + q] = as;
}

// ---------------- fill: M_ij = alpha_i*(cs[i]*(Co[qu]+Co[qv]) - sn[i]*(So[qu]+So[qv]))
// u = (2(i-j)-1) mod 1024, v = (2(i+j)+1) mod 1024 (both odd); q = m>>1.
// grid (8, NSTEPS): 32 rows per CTA. Epilogue splits to bf16 hi/lo.
__global__ void k_fill(void) {
    __shared__ float Co[512], So[512];
    const int s = blockIdx.y, rb = blockIdx.x, t = threadIdx.x;
#pragma unroll
    for (int i = 0; i < 2; i++) {
        Co[t + i * 256] = g_F[s * 1024 + t + i * 256];
        So[t + i * 256] = g_F[s * 1024 + 512 + t + i * 256];
    }
    __syncthreads();

    const int r  = rb * 32 + (t >> 3);
    const int j0 = (t & 7) * 32;
    const float ar  = (r == 0) ? 0.70710678118654752f : 1.0f;
    const float cr  = ar * g_CS[r];
    const float sr  = ar * g_SN[r];

    __nv_bfloat16* mh = g_Mh + ((size_t)s * N + r) * N;
    __nv_bfloat16* ml = g_Ml + ((size_t)s * N + r) * N;

#pragma unroll
    for (int g = 0; g < 8; g++) {
        float vals[4];
#pragma unroll
        for (int jj = 0; jj < 4; jj++) {
            int j = j0 + g * 4 + jj;
            int qu = ((2 * (r - j) - 1) & 1023) >> 1;
            int qv = ((2 * (r + j) + 1) & 1023) >> 1;
            vals[jj] = cr * (Co[qu] + Co[qv]) - sr * (So[qu] + So[qv]);
        }
        float4 v4 = make_float4(vals[0], vals[1], vals[2], vals[3]);
        uint2 H, L;
        split4(v4, H, L);
        *(uint2*)&mh[j0 + g * 4] = H;
        *(uint2*)&ml[j0 + g * 4] = L;
    }
}

// ---------------- MMA kernel (R12 champion, verbatim) ----------------
// grid (NIMG, 2, 2) = (z, h, nh); 256 threads; warp grid 4m x 2n; warp tile 32x64.
// MODE 1: T[z](h,nh) = M[s](h rows) * X[z]        (B = fp32 X, split in-kernel)
// MODE 2: out[z](h,nh) = T[z](h rows) * M[s]^T    (A = fp32 T, split in-kernel)
template <int MODE>
__global__ __launch_bounds__(256, 2) void k_mm(const float* __restrict__ Xf,
                                               float* __restrict__ Out,
                                               const int* __restrict__ steps) {
    extern __shared__ char sm[];
    const int z = blockIdx.x, h = blockIdx.y, nh = blockIdx.z;
    const int s = steps[z / 3];
    const int t = threadIdx.x, lane = t & 31, wid = t >> 5;
    const int wm = wid >> 1, wn = wid & 1;
    const uint32_t sb = smem_u32(sm);
    const int lr = lane & 15, lc8 = (lane >> 4) * 8;

    constexpr int BUFSZ = (MODE == 1) ? M1_BUF : M2_BUF;

    const char* Mh_g = (const char*)(g_Mh + (size_t)s * N * N);
    const char* Ml_g = (const char*)(g_Ml + (size_t)s * N * N);
    const float* F_g = (MODE == 1) ? (Xf + (size_t)z * N * N)
                                   : (g_T + (size_t)z * N * N);

    auto stage = [&](int kc, int b) {
        const uint32_t bo = sb + b * BUFSZ;
        if (MODE == 1) {
#pragma unroll
            for (int i = 0; i < 2; i++) {
                int c = t + i * 256, r = c >> 2, q = c & 3;
                size_t go = (size_t)(h * 128 + r) * 512 + kc * 64 + q * 16;
                cp16(bo + M1_AH + r * 80 + q * 16, Mh_g + go);
                cp16(bo + M1_AL + r * 80 + q * 16, Ml_g + go);
            }
#pragma unroll
            for (int i = 0; i < 4; i++) {
                int c = t + i * 256, r = c >> 5, q = c & 31;
                size_t go = (size_t)(kc * 32 + r) * 1024 + nh * 512 + q * 16;
                cp16(bo + M1_BS + r * 528 + q * 16, (const char*)F_g + go);
            }
        } else {
#pragma unroll
            for (int i = 0; i < 4; i++) {
                int c = t + i * 256, r = c >> 3, q = c & 7;
                size_t go = (size_t)(h * 128 + r) * 1024 + kc * 128 + q * 16;
                cp16(bo + M2_AS + r * 144 + q * 16, (const char*)F_g + go);
            }
#pragma unroll
            for (int i = 0; i < 2; i++) {
                int c = t + i * 256, r = c >> 2, q = c & 3;
                size_t go = (size_t)(nh * 128 + r) * 512 + kc * 64 + q * 16;
                cp16(bo + M2_BH + r * 80 + q * 16, Mh_g + go);
                cp16(bo + M2_BL + r * 80 + q * 16, Ml_g + go);
            }
        }
        cp_commit();
    };

    float acc[2][8][4];
#pragma unroll
    for (int a = 0; a < 2; a++)
#pragma unroll
        for (int b = 0; b < 8; b++)
#pragma unroll
            for (int c = 0; c < 4; c++) acc[a][b][c] = 0.0f;

    stage(0, 0);

#pragma unroll 1
    for (int kc = 0; kc < 8; kc++) {
        cp_wait0();
        __syncthreads();
        if (kc < 7) stage(kc + 1, (kc + 1) & 1);
        const uint32_t bo = sb + (kc & 1) * BUFSZ;
        const char* bufc = sm + (kc & 1) * BUFSZ;

        if (MODE == 1) {
            int r = t >> 3, cs = (t & 7) * 16;
            const float* src = (const float*)(bufc + M1_BS) + r * 132 + cs;
            char* dh = sm + M1_CBH + (r * 136 + cs) * 2;
            char* dl = sm + M1_CBL + (r * 136 + cs) * 2;
#pragma unroll
            for (int g = 0; g < 2; g++) {
                float4 v0 = *(const float4*)&src[g * 8];
                float4 v1 = *(const float4*)&src[g * 8 + 4];
                float v[8] = {v0.x, v0.y, v0.z, v0.w, v1.x, v1.y, v1.z, v1.w};
                uint4 H, L; split8(v, H, L);
                *(uint4*)(dh + g * 16) = H;
                *(uint4*)(dl + g * 16) = L;
            }
        } else {
            int r = t >> 1, cs = (t & 1) * 16;
            const float* src = (const float*)(bufc + M2_AS) + r * 36 + cs;
            char* dh = sm + M2_CAH + (r * 40 + cs) * 2;
            char* dl = sm + M2_CAL + (r * 40 + cs) * 2;
#pragma unroll
            for (int g = 0; g < 2; g++) {
                float4 v0 = *(const float4*)&src[g * 8];
                float4 v1 = *(const float4*)&src[g * 8 + 4];
                float v[8] = {v0.x, v0.y, v0.z, v0.w, v1.x, v1.y, v1.z, v1.w};
                uint4 H, L; split8(v, H, L);
                *(uint4*)(dh + g * 16) = H;
                *(uint4*)(dl + g * 16) = L;
            }
        }
        __syncthreads();

#pragma unroll
        for (int ks = 0; ks < 2; ks++) {
            uint32_t Ah[2][4], Al2[2][4], Bf[4][4];
#pragma unroll
            for (int mi = 0; mi < 2; mi++) {
                uint32_t a;
                if (MODE == 1)
                    a = bo + M1_AH + ((wm * 32 + mi * 16 + lr) * 40 + ks * 16 + lc8) * 2;
                else
                    a = sb + M2_CAH + ((wm * 32 + mi * 16 + lr) * 40 + ks * 16 + lc8) * 2;
                ldsm4(Ah[mi], a);
                ldsm4(Al2[mi], a + ((MODE == 1) ? (M1_AL - M1_AH) : (M2_CAL - M2_CAH)));
            }
#pragma unroll
            for (int nj = 0; nj < 4; nj++) {
                if (MODE == 1) {
                    uint32_t a = sb + M1_CBH + ((ks * 16 + lr) * 136 + wn * 64 + nj * 16 + lc8) * 2;
                    ldsm4t(Bf[nj], a);
                } else {
                    uint32_t a = bo + M2_BH + ((wn * 64 + nj * 16 + lr) * 40 + ks * 16 + lc8) * 2;
                    ldsm4(Bf[nj], a);
                }
            }
            const int p0 = 0, p1 = (MODE == 1) ? 1 : 2;
            const int p2 = (MODE == 1) ? 2 : 1, p3 = 3;
#pragma unroll
            for (int mi = 0; mi < 2; mi++)
#pragma unroll
                for (int nj = 0; nj < 4; nj++) {
                    mma_bf16(acc[mi][nj * 2],     Ah[mi], Bf[nj][p0], Bf[nj][p1]);
                    mma_bf16(acc[mi][nj * 2 + 1], Ah[mi], Bf[nj][p2], Bf[nj][p3]);
                }
#pragma unroll
            for (int mi = 0; mi < 2; mi++)
#pragma unroll
                for (int nj = 0; nj < 4; nj++) {
                    mma_bf16(acc[mi][nj * 2],     Al2[mi], Bf[nj][p0], Bf[nj][p1]);
                    mma_bf16(acc[mi][nj * 2 + 1], Al2[mi], Bf[nj][p2], Bf[nj][p3]);
                }
#pragma unroll
            for (int nj = 0; nj < 4; nj++) {
                if (MODE == 1) {
                    uint32_t a = sb + M1_CBL + ((ks * 16 + lr) * 136 + wn * 64 + nj * 16 + lc8) * 2;
                    ldsm4t(Bf[nj], a);
                } else {
                    uint32_t a = bo + M2_BL + ((wn * 64 + nj * 16 + lr) * 40 + ks * 16 + lc8) * 2;
                    ldsm4(Bf[nj], a);
                }
            }
#pragma unroll
            for (int mi = 0; mi < 2; mi++)
#pragma unroll
                for (int nj = 0; nj < 4; nj++) {
                    mma_bf16(acc[mi][nj * 2],     Ah[mi], Bf[nj][p0], Bf[nj][p1]);
                    mma_bf16(acc[mi][nj * 2 + 1], Ah[mi], Bf[nj][p2], Bf[nj][p3]);
                }
        }
        __syncthreads();
    }

    float* dst = ((MODE == 1) ? g_T : Out) + (size_t)z * N * N;
#pragma unroll
    for (int mi = 0; mi < 2; mi++)
#pragma unroll
        for (int nf = 0; nf < 8; nf++) {
            int col = nh * 128 + wn * 64 + nf * 8 + (lane & 3) * 2;
#pragma unroll
            for (int rg = 0; rg < 2; rg++) {
                int row = h * 128 + wm * 32 + mi * 16 + rg * 8 + (lane >> 2);
                *(float2*)&dst[(size_t)row * N + col] =
                    make_float2(acc[mi][nf][rg * 2], acc[mi][nf][rg * 2 + 1]);
            }
        }
}

// ---------------- host ----------------
extern "C" void kernel_launch(void* const* d_in, const int* in_sizes, int n_in,
                              void* d_out, int out_size) {
    const float* x = nullptr;
    const float* sigmas = nullptr;
    const int* steps = nullptr;
    for (int i = 0; i < n_in; i++) {
        if (in_sizes[i] == NSTEPS)      sigmas = (const float*)d_in[i];
        else if (in_sizes[i] == 128)    steps  = (const int*)d_in[i];
        else                            x      = (const float*)d_in[i];
    }
    float* out = (float*)d_out;

    cudaFuncSetAttribute(k_mm<1>, cudaFuncAttributeMaxDynamicSharedMemorySize, M1_SMEM);
    cudaFuncSetAttribute(k_mm<2>, cudaFuncAttributeMaxDynamicSharedMemorySize, M2_SMEM);

    k_init<<<NSTEPS, 256>>>(sigmas);
    k_F<<<dim3(NSTEPS, 2), 256>>>();
    k_fill<<<dim3(8, NSTEPS), 256>>>();
    k_mm<1><<<dim3(NIMG, 2, 2), 256, M1_SMEM>>>(x, nullptr, steps);
    k_mm<2><<<dim3(NIMG, 2, 2), 256, M2_SMEM>>>(nullptr, out, steps);
}

// round 17
// speedup vs baseline: 1.0592x; 1.0256x over previous
#include <cuda_runtime.h>
#include <cuda_bf16.h>
#include <math.h>
#include <stdint.h>

namespace {
constexpr int N      = 256;
constexpr int NSTEPS = 32;
constexpr int NIMG   = 384;                  // 128 batch * 3 channels

// fp32 M-builder tile
constexpr int BM = 128, BN = 128, BK = 16;
constexpr int LDSW = BM + 4;

// ---- warp-specialized k_mm smem (3-stage ring) ----
// MODE 1 stage: A=M hi 0(10240) | A lo 10240 | B conv hi 20480 (8704, stride 136) | B conv lo 29184
constexpr int ST1   = 37888;
constexpr int SM1   = 3 * ST1;               // 113664
// MODE 2 stage: A conv hi 0(10240, stride 40) | A conv lo 10240 | B=M hi 20480 | B lo 30720
constexpr int ST2   = 40960;
constexpr int SM2   = 3 * ST2;               // 122880
}

// ---------------- device globals ----------------
__device__ float g_D[N * N];
__device__ float g_E[NSTEPS * N];
__device__ __align__(16) __nv_bfloat16 g_Mh[NSTEPS * N * N];
__device__ __align__(16) __nv_bfloat16 g_Ml[NSTEPS * N * N];
__device__ __align__(16) float g_T[NIMG * N * N];     // fp32 intermediate

// ---------------- helpers ----------------
__device__ __forceinline__ uint32_t smem_u32(const void* p) {
    uint32_t a;
    asm("{ .reg .u64 t; cvta.to.shared.u64 t, %1; cvt.u32.u64 %0, t; }" : "=r"(a) : "l"(p));
    return a;
}
__device__ __forceinline__ void cp16(uint32_t s, const void* g) {
    asm volatile("cp.async.cg.shared.global [%0], [%1], 16;" :: "r"(s), "l"(g) : "memory");
}
__device__ __forceinline__ void cp_commit() {
    asm volatile("cp.async.commit_group;" ::: "memory");
}
__device__ __forceinline__ void cp_wait0() {
    asm volatile("cp.async.wait_group 0;" ::: "memory");
}
__device__ __forceinline__ void bar_sync(int id) {
    asm volatile("bar.sync %0, 512;" :: "r"(id) : "memory");
}
__device__ __forceinline__ void bar_arrive(int id) {
    asm volatile("bar.arrive %0, 512;" :: "r"(id) : "memory");
}
__device__ __forceinline__ void ldsm4(uint32_t* r, uint32_t a) {
    asm volatile("ldmatrix.sync.aligned.m8n8.x4.shared.b16 {%0,%1,%2,%3}, [%4];"
                 : "=r"(r[0]), "=r"(r[1]), "=r"(r[2]), "=r"(r[3]) : "r"(a));
}
__device__ __forceinline__ void ldsm4t(uint32_t* r, uint32_t a) {
    asm volatile("ldmatrix.sync.aligned.m8n8.x4.trans.shared.b16 {%0,%1,%2,%3}, [%4];"
                 : "=r"(r[0]), "=r"(r[1]), "=r"(r[2]), "=r"(r[3]) : "r"(a));
}
__device__ __forceinline__ void mma_bf16(float* d, const uint32_t* a, uint32_t b0, uint32_t b1) {
    asm volatile(
        "mma.sync.aligned.m16n8k16.row.col.f32.bf16.bf16.f32 "
        "{%0,%1,%2,%3}, {%4,%5,%6,%7}, {%8,%9}, {%0,%1,%2,%3};"
        : "+f"(d[0]), "+f"(d[1]), "+f"(d[2]), "+f"(d[3])
        : "r"(a[0]), "r"(a[1]), "r"(a[2]), "r"(a[3]), "r"(b0), "r"(b1));
}
__device__ __forceinline__ uint32_t pkbf2(float a, float b) {
    __nv_bfloat162 t = __floats2bfloat162_rn(a, b);
    return reinterpret_cast<uint32_t&>(t);
}
__device__ __forceinline__ void split8(const float* v, uint4& H, uint4& L) {
    float h[8], l[8];
#pragma unroll
    for (int i = 0; i < 8; i++) {
        __nv_bfloat16 b = __float2bfloat16_rn(v[i]);
        h[i] = __bfloat162float(b);
        l[i] = v[i] - h[i];
    }
    H = make_uint4(pkbf2(h[0], h[1]), pkbf2(h[2], h[3]), pkbf2(h[4], h[5]), pkbf2(h[6], h[7]));
    L = make_uint4(pkbf2(l[0], l[1]), pkbf2(l[2], l[3]), pkbf2(l[4], l[5]), pkbf2(l[6], l[7]));
}
__device__ __forceinline__ void split4(float4 v, uint2& H, uint2& L) {
    float vv[4] = {v.x, v.y, v.z, v.w};
    float h[4], l[4];
#pragma unroll
    for (int i = 0; i < 4; i++) {
        __nv_bfloat16 b = __float2bfloat16_rn(vv[i]);
        h[i] = __bfloat162float(b);
        l[i] = vv[i] - h[i];
    }
    H = make_uint2(pkbf2(h[0], h[1]), pkbf2(h[2], h[3]));
    L = make_uint2(pkbf2(l[0], l[1]), pkbf2(l[2], l[3]));
}

// ---------------- init: D and E (R12 proven) ----------------
__global__ void k_init(const float* __restrict__ sigmas) {
    int k = blockIdx.x, n = threadIdx.x;
    int p = ((2 * n + 1) * k) & (4 * N - 1);
    double v = sqrt(2.0 / (double)N) * cos(M_PI * (double)p / (double)(2 * N));
    if (k == 0) v *= 0.7071067811865476;
    g_D[k * N + n] = (float)v;
    if (k < NSTEPS) {
        float sig = sigmas[k];
        float t = 0.5f * sig * sig;
        float f = (float)M_PI * (float)n / (float)N;
        g_E[k * N + n] = expf(-f * f * t);
    }
}

// ---------------- fp32 builder: M_s = (D diag(e)) D, split epilogue (R12) -----
typedef unsigned long long u64;
__device__ __forceinline__ u64 pack2(float x, float y) {
    u64 r; asm("mov.b64 %0, {%1, %2};" : "=l"(r) : "f"(x), "f"(y)); return r;
}
__device__ __forceinline__ void unpack2(u64 v, float& x, float& y) {
    asm("mov.b64 {%0, %1}, %2;" : "=f"(x), "=f"(y) : "l"(v));
}
__device__ __forceinline__ void ffma2(u64& d, u64 a, u64 b) {
    asm("fma.rn.f32x2 %0, %1, %2, %0;" : "+l"(d) : "l"(a), "l"(b));
}

__global__ __launch_bounds__(256, 2) void k_gemm0() {
    __shared__ float As[BK][LDSW];
    __shared__ float Bs[BK][LDSW];
    const int z = blockIdx.z;
    const float* A = g_D;
    const float* B = g_D;
    const float* e = g_E + z * N;
    __nv_bfloat16* Ch = g_Mh + (size_t)z * N * N;
    __nv_bfloat16* Cl = g_Ml + (size_t)z * N * N;

    const int m0 = blockIdx.y * BM, n0 = blockIdx.x * BN;
    const int tid = threadIdx.x;
    const int ty = tid >> 4, tx = tid & 15;
    const int lr = (tid * 2) >> 2, lc = (tid * 2) & 3;
    const int bkr = (tid * 2) >> 5, bnc = (tid * 2) & 31;

    u64 acc[8][4];
#pragma unroll
    for (int i = 0; i < 8; i++)
#pragma unroll
        for (int j = 0; j < 4; j++) acc[i][j] = 0ull;

    for (int k0 = 0; k0 < N; k0 += BK) {
        float4 a0 = *(const float4*)&A[(size_t)(m0 + lr) * N + k0 + lc * 4];
        float4 a1 = *(const float4*)&A[(size_t)(m0 + lr) * N + k0 + lc * 4 + 4];
        a0.x *= e[k0 + lc * 4 + 0]; a0.y *= e[k0 + lc * 4 + 1];
        a0.z *= e[k0 + lc * 4 + 2]; a0.w *= e[k0 + lc * 4 + 3];
        a1.x *= e[k0 + lc * 4 + 4]; a1.y *= e[k0 + lc * 4 + 5];
        a1.z *= e[k0 + lc * 4 + 6]; a1.w *= e[k0 + lc * 4 + 7];
        float4 b0 = *(const float4*)&B[(size_t)(k0 + bkr) * N + n0 + bnc * 4];
        float4 b1 = *(const float4*)&B[(size_t)(k0 + bkr) * N + n0 + bnc * 4 + 4];
        __syncthreads();
        As[lc * 4 + 0][lr] = a0.x; As[lc * 4 + 1][lr] = a0.y;
        As[lc * 4 + 2][lr] = a0.z; As[lc * 4 + 3][lr] = a0.w;
        As[lc * 4 + 4][lr] = a1.x; As[lc * 4 + 5][lr] = a1.y;
        As[lc * 4 + 6][lr] = a1.z; As[lc * 4 + 7][lr] = a1.w;
        *(float4*)&Bs[bkr][bnc * 4]     = b0;
        *(float4*)&Bs[bkr][bnc * 4 + 4] = b1;
        __syncthreads();
#pragma unroll
        for (int kk = 0; kk < BK; kk++) {
            float4 av0 = *(const float4*)&As[kk][ty * 4];
            float4 av1 = *(const float4*)&As[kk][64 + ty * 4];
            float4 bv0 = *(const float4*)&Bs[kk][tx * 4];
            float4 bv1 = *(const float4*)&Bs[kk][64 + tx * 4];
            u64 a2[8] = {pack2(av0.x, av0.x), pack2(av0.y, av0.y), pack2(av0.z, av0.z),
                         pack2(av0.w, av0.w), pack2(av1.x, av1.x), pack2(av1.y, av1.y),
                         pack2(av1.z, av1.z), pack2(av1.w, av1.w)};
            u64 b2[4] = {pack2(bv0.x, bv0.y), pack2(bv0.z, bv0.w),
                         pack2(bv1.x, bv1.y), pack2(bv1.z, bv1.w)};
#pragma unroll
            for (int i = 0; i < 8; i++)
#pragma unroll
                for (int j = 0; j < 4; j++) ffma2(acc[i][j], a2[i], b2[j]);
        }
    }
#pragma unroll
    for (int i = 0; i < 8; i++) {
        const int row = m0 + ((i < 4) ? (ty * 4 + i) : (64 + ty * 4 + (i - 4)));
        float4 c0, c1;
        unpack2(acc[i][0], c0.x, c0.y); unpack2(acc[i][1], c0.z, c0.w);
        unpack2(acc[i][2], c1.x, c1.y); unpack2(acc[i][3], c1.z, c1.w);
        uint2 H0, L0, H1, L1;
        split4(c0, H0, L0);
        split4(c1, H1, L1);
        *(uint2*)&Ch[(size_t)row * N + n0 + tx * 4]      = H0;
        *(uint2*)&Cl[(size_t)row * N + n0 + tx * 4]      = L0;
        *(uint2*)&Ch[(size_t)row * N + n0 + 64 + tx * 4] = H1;
        *(uint2*)&Cl[(size_t)row * N + n0 + 64 + tx * 4] = L1;
    }
}

// ---------------- warp-specialized MMA kernel ----------------
// 512 threads: warps 0-7 consumers (champion 4m x 2n, warp tile 32x64),
// warps 8-15 producers. 3-stage smem ring; named barriers full=1+d, empty=4+d.
// MODE 1: T[z](h,nh) = M[s](h rows) * X[z]       (B = X fp32 -> split by producers)
// MODE 2: out[z](h,nh) = T[z](h rows) * M[s]^T   (A = T fp32 -> split by producers)
template <int MODE>
__global__ __launch_bounds__(512, 1) void k_mm(const float* __restrict__ Xf,
                                               float* __restrict__ Out,
                                               const int* __restrict__ steps) {
    extern __shared__ char sm[];
    const int z = blockIdx.x, h = blockIdx.y, nh = blockIdx.z;
    const int s = steps[z / 3];
    const int t = threadIdx.x, wid = t >> 5;
    const uint32_t sb = smem_u32(sm);

    constexpr int ST = (MODE == 1) ? ST1 : ST2;
    constexpr int BLO = (MODE == 1) ? 8704 : 10240;   // B lo offset from B hi

    const char* Mh_g = (const char*)(g_Mh + (size_t)s * N * N);
    const char* Ml_g = (const char*)(g_Ml + (size_t)s * N * N);
    const float* F_g = (MODE == 1) ? (Xf + (size_t)z * N * N)
                                   : (g_T + (size_t)z * N * N);

    if (wid >= 8) {
        // ================= producers =================
        const int pt = t - 256;
        // M-tile cp target: MODE1 -> A region (stage+0), MODE2 -> B region (stage+20480)
        const int moff = (MODE == 1) ? 0 : 20480;
        const int mrow = ((MODE == 1) ? h : nh) * 128;
        // fp32 ownership (LDG + convert): MODE1 32x128 (r=pt>>3), MODE2 128x32 (r=pt>>1)
        const int fr = (MODE == 1) ? (pt >> 3) : (pt >> 1);
        const int fc = (MODE == 1) ? ((pt & 7) * 16) : ((pt & 1) * 16);

#pragma unroll 1
        for (int kc = 0; kc < 8; kc++) {
            const int d = kc - (kc >= 3) * 3 - (kc >= 6) * 3;   // kc % 3
            if (kc >= 3) bar_sync(4 + d);
            const uint32_t stb = sb + d * ST;
            // cp.async the M hi/lo tile (128 rows x 64B at col kc*64)
#pragma unroll
            for (int i = 0; i < 2; i++) {
                int c = pt + i * 256, r = c >> 2, q = c & 3;
                size_t go = (size_t)(mrow + r) * 512 + kc * 64 + q * 16;
                cp16(stb + moff + r * 80 + q * 16, Mh_g + go);
                cp16(stb + moff + 10240 + r * 80 + q * 16, Ml_g + go);
            }
            cp_commit();
            // LDG own 16 fp32 values
            const float* p = (MODE == 1)
                ? (F_g + (size_t)(kc * 32 + fr) * N + nh * 128 + fc)
                : (F_g + (size_t)(h * 128 + fr) * N + kc * 32 + fc);
            float4 pf0 = *(const float4*)p;
            float4 pf1 = *(const float4*)(p + 4);
            float4 pf2 = *(const float4*)(p + 8);
            float4 pf3 = *(const float4*)(p + 12);
            // convert + STS into this stage's conv dest
            {
                char* dh;
                char* dl;
                if (MODE == 1) {
                    dh = sm + d * ST + 20480 + (fr * 136 + fc) * 2;
                    dl = dh + 8704;
                } else {
                    dh = sm + d * ST + (fr * 40 + fc) * 2;
                    dl = dh + 10240;
                }
                float v0[8] = {pf0.x, pf0.y, pf0.z, pf0.w, pf1.x, pf1.y, pf1.z, pf1.w};
                float v1[8] = {pf2.x, pf2.y, pf2.z, pf2.w, pf3.x, pf3.y, pf3.z, pf3.w};
                uint4 H, L;
                split8(v0, H, L);
                *(uint4*)dh = H; *(uint4*)dl = L;
                split8(v1, H, L);
                *(uint4*)(dh + 16) = H; *(uint4*)(dl + 16) = L;
            }
            cp_wait0();          // own M cp complete before publishing
            bar_arrive(1 + d);   // stage d full
        }
        return;
    }

    // ================= consumers =================
    const int lane = t & 31;
    const int wm = wid >> 1, wn = wid & 1;
    const int lr = lane & 15, lc8 = (lane >> 4) * 8;

    float acc[2][8][4];
#pragma unroll
    for (int a = 0; a < 2; a++)
#pragma unroll
        for (int b = 0; b < 8; b++)
#pragma unroll
            for (int c = 0; c < 4; c++) acc[a][b][c] = 0.0f;

#pragma unroll 1
    for (int kc = 0; kc < 8; kc++) {
        const int d = kc - (kc >= 3) * 3 - (kc >= 6) * 3;   // kc % 3
        bar_sync(1 + d);                                    // wait stage full
        const uint32_t stb = sb + d * ST;
        // A base: MODE1 = M tiles (stage+0), MODE2 = conv dest (stage+0). Both +0/+10240.
        const uint32_t abase = stb;
        // B base: both modes stage+20480; lo at +BLO.
        const uint32_t bbase = stb + 20480;

#pragma unroll
        for (int ks = 0; ks < 2; ks++) {
            uint32_t Ah[2][4], Al2[2][4], Bf[4][4];
#pragma unroll
            for (int mi = 0; mi < 2; mi++) {
                uint32_t a = abase + ((wm * 32 + mi * 16 + lr) * 40 + ks * 16 + lc8) * 2;
                ldsm4(Ah[mi], a);
                ldsm4(Al2[mi], a + 10240);
            }
#pragma unroll
            for (int nj = 0; nj < 4; nj++) {
                if (MODE == 1) {
                    uint32_t a = bbase + ((ks * 16 + lr) * 136 + wn * 64 + nj * 16 + lc8) * 2;
                    ldsm4t(Bf[nj], a);
                } else {
                    uint32_t a = bbase + ((wn * 64 + nj * 16 + lr) * 40 + ks * 16 + lc8) * 2;
                    ldsm4(Bf[nj], a);
                }
            }
            const int p0 = 0, p1 = (MODE == 1) ? 1 : 2;
            const int p2 = (MODE == 1) ? 2 : 1, p3 = 3;
            // pass 1: Ah x Bh
#pragma unroll
            for (int mi = 0; mi < 2; mi++)
#pragma unroll
                for (int nj = 0; nj < 4; nj++) {
                    mma_bf16(acc[mi][nj * 2],     Ah[mi], Bf[nj][p0], Bf[nj][p1]);
                    mma_bf16(acc[mi][nj * 2 + 1], Ah[mi], Bf[nj][p2], Bf[nj][p3]);
                }
            // pass 2: Al x Bh
#pragma unroll
            for (int mi = 0; mi < 2; mi++)
#pragma unroll
                for (int nj = 0; nj < 4; nj++) {
                    mma_bf16(acc[mi][nj * 2],     Al2[mi], Bf[nj][p0], Bf[nj][p1]);
                    mma_bf16(acc[mi][nj * 2 + 1], Al2[mi], Bf[nj][p2], Bf[nj][p3]);
                }
            // B lo
#pragma unroll
            for (int nj = 0; nj < 4; nj++) {
                if (MODE == 1) {
                    uint32_t a = bbase + BLO + ((ks * 16 + lr) * 136 + wn * 64 + nj * 16 + lc8) * 2;
                    ldsm4t(Bf[nj], a);
                } else {
                    uint32_t a = bbase + BLO + ((wn * 64 + nj * 16 + lr) * 40 + ks * 16 + lc8) * 2;
                    ldsm4(Bf[nj], a);
                }
            }
            // pass 3: Ah x Bl
#pragma unroll
            for (int mi = 0; mi < 2; mi++)
#pragma unroll
                for (int nj = 0; nj < 4; nj++) {
                    mma_bf16(acc[mi][nj * 2],     Ah[mi], Bf[nj][p0], Bf[nj][p1]);
                    mma_bf16(acc[mi][nj * 2 + 1], Ah[mi], Bf[nj][p2], Bf[nj][p3]);
                }
        }
        bar_arrive(4 + d);        // stage d empty
    }

    // epilogue: fp32 store (T or Out)
    float* dst = ((MODE == 1) ? g_T : Out) + (size_t)z * N * N;
#pragma unroll
    for (int mi = 0; mi < 2; mi++)
#pragma unroll
        for (int nf = 0; nf < 8; nf++) {
            int col = nh * 128 + wn * 64 + nf * 8 + (lane & 3) * 2;
#pragma unroll
            for (int rg = 0; rg < 2; rg++) {
                int row = h * 128 + wm * 32 + mi * 16 + rg * 8 + (lane >> 2);
                *(float2*)&dst[(size_t)row * N + col] =
                    make_float2(acc[mi][nf][rg * 2], acc[mi][nf][rg * 2 + 1]);
            }
        }
}

// ---------------- host ----------------
extern "C" void kernel_launch(void* const* d_in, const int* in_sizes, int n_in,
                              void* d_out, int out_size) {
    const float* x = nullptr;
    const float* sigmas = nullptr;
    const int* steps = nullptr;
    for (int i = 0; i < n_in; i++) {
        if (in_sizes[i] == NSTEPS)      sigmas = (const float*)d_in[i];
        else if (in_sizes[i] == 128)    steps  = (const int*)d_in[i];
        else                            x      = (const float*)d_in[i];
    }
    float* out = (float*)d_out;

    cudaFuncSetAttribute(k_mm<1>, cudaFuncAttributeMaxDynamicSharedMemorySize, SM1);
    cudaFuncSetAttribute(k_mm<2>, cudaFuncAttributeMaxDynamicSharedMemorySize, SM2);

    k_init<<<N, N>>>(sigmas);
    k_gemm0<<<dim3(N / BN, N / BM, NSTEPS), 256>>>();
    k_mm<1><<<dim3(NIMG, 2, 2), 512, SM1>>>(x, nullptr, steps);
    k_mm<2><<<dim3(NIMG, 2, 2), 512, SM2>>>(nullptr, out, steps);
}